// round 15
// baseline (speedup 1.0000x reference)
#include <cuda_runtime.h>
#include <cuda_fp16.h>
#include <cstdint>

#define Bn 4
#define Sn 2048
#define Dn 1024
#define Hn 16
#define DH 64
#define NELEM (Bn * Hn * Sn * DH)
#define LOG2E 1.4426950408889634f

typedef unsigned long long u64;
typedef unsigned int u32;

// fp16 scratch (allocation-free rule: __device__ globals)
__device__ __half g_xf[Bn * Sn * Dn];
__device__ __half g_wf[3 * Dn * Dn];
__device__ __half g_qf[NELEM];
__device__ __half g_kf[NELEM];
__device__ __half g_vf[NELEM];
__device__ __half g_mh[Bn * Sn];   // mask * log2e, fp16

// ---------------- helpers ----------------
__device__ __forceinline__ u32 smem_u32(const void* p) {
    u32 a;
    asm("{ .reg .u64 t; cvta.to.shared.u64 t, %1; cvt.u32.u64 %0, t; }" : "=r"(a) : "l"(p));
    return a;
}
__device__ __forceinline__ void ldsm_x4(u32& r0, u32& r1, u32& r2, u32& r3, u32 addr) {
    asm volatile("ldmatrix.sync.aligned.m8n8.x4.shared.b16 {%0,%1,%2,%3}, [%4];"
                 : "=r"(r0), "=r"(r1), "=r"(r2), "=r"(r3) : "r"(addr));
}
__device__ __forceinline__ void ldsm_x4_t(u32& r0, u32& r1, u32& r2, u32& r3, u32 addr) {
    asm volatile("ldmatrix.sync.aligned.m8n8.x4.trans.shared.b16 {%0,%1,%2,%3}, [%4];"
                 : "=r"(r0), "=r"(r1), "=r"(r2), "=r"(r3) : "r"(addr));
}
__device__ __forceinline__ void mma_f16(float* c, const u32* a, u32 b0, u32 b1) {
    asm volatile("mma.sync.aligned.m16n8k16.row.col.f32.f16.f16.f32 "
        "{%0,%1,%2,%3}, {%4,%5,%6,%7}, {%8,%9}, {%0,%1,%2,%3};"
        : "+f"(c[0]), "+f"(c[1]), "+f"(c[2]), "+f"(c[3])
        : "r"(a[0]), "r"(a[1]), "r"(a[2]), "r"(a[3]), "r"(b0), "r"(b1));
}
// fp16-accumulator MMA: D = {d0,d1} packed half2 pairs (row g / row g+8)
__device__ __forceinline__ void mma_f16a(u32& d0, u32& d1, const u32* a, u32 b0, u32 b1) {
    asm volatile("mma.sync.aligned.m16n8k16.row.col.f16.f16.f16.f16 "
        "{%0,%1}, {%2,%3,%4,%5}, {%6,%7}, {%0,%1};"
        : "+r"(d0), "+r"(d1)
        : "r"(a[0]), "r"(a[1]), "r"(a[2]), "r"(a[3]), "r"(b0), "r"(b1));
}
__device__ __forceinline__ void cpa16(u32 s, const void* g) {
    asm volatile("cp.async.cg.shared.global [%0], [%1], 16;" :: "r"(s), "l"(g));
}
#define CP_COMMIT() asm volatile("cp.async.commit_group;" ::: "memory")
#define CP_WAIT1()  asm volatile("cp.async.wait_group 1;" ::: "memory")

__device__ __forceinline__ u32 packh2(float a, float b) {
    __half2 h = __float22half2_rn(make_float2(a, b));
    return *(u32*)&h;
}

// ---------------------------------------------------------------------------
// input conversions: X -> fp16, W(q,k,v) -> fp16, mask -> fp16*log2e
// ---------------------------------------------------------------------------
__global__ __launch_bounds__(256) void convx_kernel(const float* __restrict__ X) {
    size_t i = (size_t)blockIdx.x * 256 + threadIdx.x;
    float4 v = ((const float4*)X)[i];
    uint2 o;
    o.x = packh2(v.x, v.y);
    o.y = packh2(v.z, v.w);
    ((uint2*)g_xf)[i] = o;
}
__global__ __launch_bounds__(256) void convw_kernel(
    const float* __restrict__ qw, const float* __restrict__ kw, const float* __restrict__ vw) {
    const int z = blockIdx.y;
    const float* W = (z == 0) ? qw : (z == 1) ? kw : vw;
    size_t i = (size_t)blockIdx.x * 256 + threadIdx.x;
    float4 v = ((const float4*)W)[i];
    uint2 o;
    o.x = packh2(v.x, v.y);
    o.y = packh2(v.z, v.w);
    ((uint2*)(g_wf + (size_t)z * Dn * Dn))[i] = o;
}
__global__ __launch_bounds__(256) void convm_kernel(const float* __restrict__ mask) {
    int i = blockIdx.x * 256 + threadIdx.x;   // 8192 total
    g_mh[i] = __float2half(mask[i] * LOG2E);
}

// ---------------------------------------------------------------------------
// QKV projection: C = X @ W^T + b, fp16 HMMA (fp32 accum), BK=64.
// q rows scaled by 0.125*log2(e) so attention can use exp2.
// ---------------------------------------------------------------------------
#define PBM 128
#define PBN 128
#define PBK 64
#define PST 72
#define XTILE (PBM * PST)
#define PSMEM (2 * 2 * XTILE * 2)

extern __shared__ char dynsm[];

__global__ __launch_bounds__(256, 2) void qkv_hmma_kernel(
    const float* __restrict__ qb, const float* __restrict__ kb, const float* __restrict__ vb)
{
    const int tid = threadIdx.x, lane = tid & 31, wid = tid >> 5;
    const int z = blockIdx.z;
    const int m0 = blockIdx.y * PBM, n0 = blockIdx.x * PBN;
    const int wm = wid >> 1, wn = wid & 1;
    const int g = lane >> 2, tig = lane & 3;
    const u32 smb = smem_u32(dynsm);

    const __half* Wf = g_wf + (size_t)z * Dn * Dn;
    const float* bias = (z == 0) ? qb : (z == 1) ? kb : vb;
    const float scale = (z == 0) ? 0.125f * LOG2E : 1.0f;
    __half* Of = (z == 0) ? g_qf : (z == 1) ? g_kf : g_vf;

    float C[2][8][4];
#pragma unroll
    for (int mf = 0; mf < 2; mf++)
#pragma unroll
        for (int nt = 0; nt < 8; nt++)
#pragma unroll
            for (int s = 0; s < 4; s++) C[mf][nt][s] = 0.0f;

    auto issue = [&](int ks, int st) {
        const int k0 = ks * PBK;
#pragma unroll
        for (int i = 0; i < 4; i++) {
            int ch = tid + i * 256;
            int row = ch >> 3, c8 = ch & 7;
            u32 so = smb + (u32)(st * 2 * XTILE + row * PST + c8 * 8) * 2;
            cpa16(so, g_xf + (size_t)(m0 + row) * Dn + k0 + c8 * 8);
            cpa16(so + XTILE * 2, Wf + (size_t)(n0 + row) * Dn + k0 + c8 * 8);
        }
        CP_COMMIT();
    };

    issue(0, 0);
    issue(1, 1);

    const int r = lane & 7, sub = lane >> 3;
    const int keyb = ((sub >> 1) & 1) * 8 + r;
    const int dadd = (sub & 1) * 8;

    for (int ks = 0; ks < Dn / PBK; ks++) {
        CP_WAIT1();
        __syncthreads();
        const int st = ks & 1;
        const u32 ab = smb + (u32)(st * 2 * XTILE) * 2;
#pragma unroll
        for (int j = 0; j < 4; j++) {
            u32 a[2][4];
#pragma unroll
            for (int mf = 0; mf < 2; mf++) {
                u32 ao = (u32)((wm * 32 + mf * 16 + (lane & 15)) * PST + j * 16 + (lane >> 4) * 8) * 2;
                ldsm_x4(a[mf][0], a[mf][1], a[mf][2], a[mf][3], ab + ao);
            }
            u32 bb[8][2];
#pragma unroll
            for (int p = 0; p < 4; p++) {
                u32 bo = (u32)((wn * 64 + p * 16 + keyb) * PST + j * 16 + dadd) * 2;
                ldsm_x4(bb[2 * p][0], bb[2 * p][1], bb[2 * p + 1][0], bb[2 * p + 1][1],
                        ab + XTILE * 2 + bo);
            }
#pragma unroll
            for (int mf = 0; mf < 2; mf++)
#pragma unroll
                for (int nt = 0; nt < 8; nt++) mma_f16(C[mf][nt], a[mf], bb[nt][0], bb[nt][1]);
        }
        __syncthreads();
        if (ks + 2 < Dn / PBK) issue(ks + 2, st);
    }

#pragma unroll
    for (int mf = 0; mf < 2; mf++) {
        const int r0 = m0 + wm * 32 + mf * 16 + g;
#pragma unroll
        for (int nt = 0; nt < 8; nt++) {
            const int c0 = n0 + wn * 64 + nt * 8 + 2 * tig;
            float2 bbv = *(const float2*)(bias + c0);
            const int h = c0 >> 6, dc = c0 & 63;
#pragma unroll
            for (int half = 0; half < 2; half++) {
                const int rr = r0 + half * 8;
                const int b = rr >> 11, s = rr & 2047;
                float x0 = (C[mf][nt][half * 2 + 0] + bbv.x) * scale;
                float x1 = (C[mf][nt][half * 2 + 1] + bbv.y) * scale;
                size_t off = ((size_t)((b * Hn + h) * Sn + s)) * DH + dc;
                *(u32*)(Of + off) = packh2(x0, x1);
            }
        }
    }
}

// ---------------------------------------------------------------------------
// fp16 HMMA flash attention, software-pipelined: iter t computes scores(t),
// then softmax(t) INTERLEAVED with PV(t-1) (independent registers), so PV
// HMMAs fill the MUFU/cvt stalls of the softmax. Triple-buffered smem
// stages (t%3): issue(t+2) reuses stage (t-1)%3 only after the barrier
// that follows PV(t-1). CTA = 128 thr / 4 warps; 32 q rows/warp.
// ---------------------------------------------------------------------------
#define TKV 64
#define KST 72
#define BUFE (64 * KST)
#define NT (Sn / TKV)
#define AMS_OFF (3 * 2 * BUFE * 2)      // 55296
#define ASMEM (AMS_OFF + 3 * 128)       // + fp16 mask per stage

__global__ __launch_bounds__(128, 2) void attn_hmma_kernel(float* __restrict__ outp)
{
    __half* smbuf = (__half*)dynsm;

    const int tid = threadIdx.x;
    const int lane = tid & 31;
    const int wid = tid >> 5;          // 0..3
    const int bh = blockIdx.y;
    const int b = bh >> 4, h = bh & 15;
    const int q0 = blockIdx.x * 128;
    const int g = lane >> 2;
    const int tig = lane & 3;

    const u32 smb = smem_u32(smbuf);
    const u32 msb = smb + AMS_OFF;
    const __half* mrow = g_mh + (size_t)b * Sn;

    // ---- stage Q (128x64 fp16), ldmatrix into regs ----
#pragma unroll
    for (int i = 0; i < 8; i++) {
        int ch = tid + i * 128;
        int row = ch >> 3, c8 = ch & 7;
        *(uint4*)(smbuf + row * KST + c8 * 8) =
            *(const uint4*)(g_qf + ((size_t)bh * Sn + q0 + row) * DH + c8 * 8);
    }
    __syncthreads();

    u32 qf[2][4][4];
#pragma unroll
    for (int mf = 0; mf < 2; mf++) {
        int row = wid * 32 + mf * 16 + (lane & 15);
        int cb = (lane >> 4) * 8;
#pragma unroll
        for (int j = 0; j < 4; j++) {
            u32 ao = (u32)(row * KST + j * 16 + cb) * 2;
            ldsm_x4(qf[mf][j][0], qf[mf][j][1], qf[mf][j][2], qf[mf][j][3], smb + ao);
        }
    }
    __syncthreads();

    auto issue = [&](int t, int st) {
        const int t0 = t * TKV;
        const u32 sb = smb + (u32)(st * 2 * BUFE) * 2;
#pragma unroll
        for (int i = 0; i < 4; i++) {
            int ch = tid + i * 128;
            int row = ch >> 3, c8 = ch & 7;
            size_t gix = ((size_t)bh * Sn + t0 + row) * DH + c8 * 8;
            u32 so = sb + (u32)(row * KST + c8 * 8) * 2;
            cpa16(so, g_kf + gix);
            cpa16(so + BUFE * 2, g_vf + gix);
        }
        if (tid < 8) cpa16(msb + st * 128 + tid * 16, mrow + t0 + tid * 8);
        CP_COMMIT();
    };

    issue(0, 0);
    issue(1, 1);

    float ctx[2][8][4];
#pragma unroll
    for (int mf = 0; mf < 2; mf++)
#pragma unroll
        for (int m = 0; m < 8; m++)
#pragma unroll
            for (int s = 0; s < 4; s++) ctx[mf][m][s] = 0.0f;
    float ls[2][2] = {{0.0f, 0.0f}, {0.0f, 0.0f}};

    const int r = lane & 7, sub = lane >> 3;
    const int keyb = ((sub >> 1) & 1) * 8 + r;       // scores B mapping
    const int dadds = (sub & 1) * 8;
    const int keyadd = (sub & 1) * 8 + r;            // PV B mapping
    const int daddv = ((sub >> 1) & 1) * 8;

    u32 Cp[2][8][2];    // P fragments of previous tile

    // scores(t) into Cn from K stage st
    auto scores = [&](int st, u32 Cn[2][8][2]) {
        const u32 kf_b = smb + (u32)(st * 2 * BUFE) * 2;
#pragma unroll
        for (int mf = 0; mf < 2; mf++)
#pragma unroll
            for (int nt = 0; nt < 8; nt++) { Cn[mf][nt][0] = 0u; Cn[mf][nt][1] = 0u; }
#pragma unroll
        for (int j = 0; j < 4; j++) {
            u32 bk[8][2];
#pragma unroll
            for (int p = 0; p < 4; p++) {
                u32 ao = (u32)((p * 16 + keyb) * KST + j * 16 + dadds) * 2;
                ldsm_x4(bk[2 * p][0], bk[2 * p][1], bk[2 * p + 1][0], bk[2 * p + 1][1], kf_b + ao);
            }
#pragma unroll
            for (int mf = 0; mf < 2; mf++)
#pragma unroll
                for (int nt = 0; nt < 8; nt++)
                    mma_f16a(Cn[mf][nt][0], Cn[mf][nt][1], qf[mf][j], bk[nt][0], bk[nt][1]);
        }
    };

    // softmax(t) in place on Cn (mask stage st)
    auto softmax = [&](int st, u32 Cn[2][8][2]) {
        const __half2* mp = (const __half2*)(dynsm + AMS_OFF + st * 128);
        __half2 lt[2][2];
        lt[0][0] = __float2half2_rn(0.0f); lt[0][1] = lt[0][0];
        lt[1][0] = lt[0][0];               lt[1][1] = lt[0][0];
#pragma unroll
        for (int nt = 0; nt < 8; nt++) {
            __half2 mh = mp[nt * 4 + tig];
#pragma unroll
            for (int mf = 0; mf < 2; mf++) {
                __half2 p0 = h2exp2(__hadd2(*(__half2*)&Cn[mf][nt][0], mh));
                __half2 p1 = h2exp2(__hadd2(*(__half2*)&Cn[mf][nt][1], mh));
                lt[mf][0] = __hadd2(lt[mf][0], p0);
                lt[mf][1] = __hadd2(lt[mf][1], p1);
                Cn[mf][nt][0] = *(u32*)&p0;
                Cn[mf][nt][1] = *(u32*)&p1;
            }
        }
#pragma unroll
        for (int mf = 0; mf < 2; mf++) {
            float2 f01 = __half22float2(lt[mf][0]);
            float2 f23 = __half22float2(lt[mf][1]);
            ls[mf][0] += f01.x + f01.y;
            ls[mf][1] += f23.x + f23.y;
        }
    };

    // ctx += P*V, P = Pv frags, V stage st
    auto pv = [&](int st, u32 Pv[2][8][2]) {
        const u32 vf_b = smb + (u32)(st * 2 * BUFE) * 2 + BUFE * 2;
#pragma unroll
        for (int j = 0; j < 4; j++) {
            u32 vv[8][2];
#pragma unroll
            for (int p = 0; p < 4; p++) {
                u32 ao = (u32)((j * 16 + keyadd) * KST + p * 16 + daddv) * 2;
                ldsm_x4_t(vv[2 * p][0], vv[2 * p][1], vv[2 * p + 1][0], vv[2 * p + 1][1], vf_b + ao);
            }
#pragma unroll
            for (int mf = 0; mf < 2; mf++)
#pragma unroll
                for (int m = 0; m < 8; m++)
                    mma_f16(ctx[mf][m], &Pv[mf][2 * j][0], vv[m][0], vv[m][1]);
        }
    };

    // ---- prologue: tile 0 (no PV yet) ----
    CP_WAIT1();
    __syncthreads();
    scores(0, Cp);
    softmax(0, Cp);
    __syncthreads();
    issue(2, 2);

    // ---- pipelined mainloop: scores(t), softmax(t) || PV(t-1) ----
#pragma unroll 1
    for (int t = 1; t < NT; t++) {
        CP_WAIT1();
        __syncthreads();
        const int stc = t % 3;
        const int stp = (t - 1) % 3;

        u32 Cn[2][8][2];
        scores(stc, Cn);
        softmax(stc, Cn);     // independent of pv() below: ptxas interleaves
        pv(stp, Cp);
#pragma unroll
        for (int mf = 0; mf < 2; mf++)
#pragma unroll
            for (int nt = 0; nt < 8; nt++) {
                Cp[mf][nt][0] = Cn[mf][nt][0];
                Cp[mf][nt][1] = Cn[mf][nt][1];
            }
        __syncthreads();
        if (t + 2 < NT) issue(t + 2, (t + 2) % 3);
    }

    // ---- epilogue: PV of last tile ----
    pv((NT - 1) % 3, Cp);

    // ---- finalize: quad-reduce row sums, normalize, store ----
#pragma unroll
    for (int mf = 0; mf < 2; mf++) {
        float l0 = ls[mf][0], l1 = ls[mf][1];
        l0 += __shfl_xor_sync(0xffffffff, l0, 1);
        l0 += __shfl_xor_sync(0xffffffff, l0, 2);
        l1 += __shfl_xor_sync(0xffffffff, l1, 1);
        l1 += __shfl_xor_sync(0xffffffff, l1, 2);
        const float inv0 = 1.0f / l0, inv1 = 1.0f / l1;

        const int row0 = q0 + wid * 32 + mf * 16 + g;
        const int row1 = row0 + 8;
        float* d0 = outp + (size_t)(b * Sn + row0) * Dn + h * DH + 2 * tig;
        float* d1 = outp + (size_t)(b * Sn + row1) * Dn + h * DH + 2 * tig;
#pragma unroll
        for (int m = 0; m < 8; m++) {
            *(float2*)(d0 + m * 8) = make_float2(ctx[mf][m][0] * inv0, ctx[mf][m][1] * inv0);
            *(float2*)(d1 + m * 8) = make_float2(ctx[mf][m][2] * inv1, ctx[mf][m][3] * inv1);
        }
    }
}

// ---------------------------------------------------------------------------
extern "C" void kernel_launch(void* const* d_in, const int* in_sizes, int n_in,
                              void* d_out, int out_size)
{
    (void)in_sizes; (void)n_in; (void)out_size;
    const float* X    = (const float*)d_in[0];
    const float* mask = (const float*)d_in[1];
    const float* qw   = (const float*)d_in[2];
    const float* qb   = (const float*)d_in[3];
    const float* kw   = (const float*)d_in[4];
    const float* kb   = (const float*)d_in[5];
    const float* vw   = (const float*)d_in[6];
    const float* vb   = (const float*)d_in[7];
    float* out = (float*)d_out;

    static int attr_done = 0;
    if (!attr_done) {
        cudaFuncSetAttribute(qkv_hmma_kernel,
                             cudaFuncAttributeMaxDynamicSharedMemorySize, PSMEM);
        cudaFuncSetAttribute(attn_hmma_kernel,
                             cudaFuncAttributeMaxDynamicSharedMemorySize, ASMEM);
        attr_done = 1;
    }

    convx_kernel<<<(Bn * Sn * Dn) / 4 / 256, 256>>>(X);
    convw_kernel<<<dim3((Dn * Dn) / 4 / 256, 3), 256>>>(qw, kw, vw);
    convm_kernel<<<(Bn * Sn) / 256, 256>>>(mask);

    qkv_hmma_kernel<<<dim3(Dn / PBN, (Bn * Sn) / PBM, 3), 256, PSMEM>>>(qb, kb, vb);

    attn_hmma_kernel<<<dim3(Sn / 128, Bn * Hn), 128, ASMEM>>>(out);
}

// round 16
// speedup vs baseline: 1.1130x; 1.1130x over previous
#include <cuda_runtime.h>
#include <cuda_fp16.h>
#include <cstdint>

#define Bn 4
#define Sn 2048
#define Dn 1024
#define Hn 16
#define DH 64
#define NELEM (Bn * Hn * Sn * DH)
#define LOG2E 1.4426950408889634f

typedef unsigned long long u64;
typedef unsigned int u32;

// fp16 scratch (allocation-free rule: __device__ globals)
__device__ __half g_xf[Bn * Sn * Dn];
__device__ __half g_wf[3 * Dn * Dn];
__device__ __half g_qf[NELEM];
__device__ __half g_kf[NELEM];
__device__ __half g_vf[NELEM];
__device__ __half g_mh[Bn * Sn];   // mask * log2e, fp16

// ---------------- helpers ----------------
__device__ __forceinline__ u32 smem_u32(const void* p) {
    u32 a;
    asm("{ .reg .u64 t; cvta.to.shared.u64 t, %1; cvt.u32.u64 %0, t; }" : "=r"(a) : "l"(p));
    return a;
}
__device__ __forceinline__ void ldsm_x4(u32& r0, u32& r1, u32& r2, u32& r3, u32 addr) {
    asm volatile("ldmatrix.sync.aligned.m8n8.x4.shared.b16 {%0,%1,%2,%3}, [%4];"
                 : "=r"(r0), "=r"(r1), "=r"(r2), "=r"(r3) : "r"(addr));
}
__device__ __forceinline__ void ldsm_x4_t(u32& r0, u32& r1, u32& r2, u32& r3, u32 addr) {
    asm volatile("ldmatrix.sync.aligned.m8n8.x4.trans.shared.b16 {%0,%1,%2,%3}, [%4];"
                 : "=r"(r0), "=r"(r1), "=r"(r2), "=r"(r3) : "r"(addr));
}
__device__ __forceinline__ void mma_f16(float* c, const u32* a, u32 b0, u32 b1) {
    asm volatile("mma.sync.aligned.m16n8k16.row.col.f32.f16.f16.f32 "
        "{%0,%1,%2,%3}, {%4,%5,%6,%7}, {%8,%9}, {%0,%1,%2,%3};"
        : "+f"(c[0]), "+f"(c[1]), "+f"(c[2]), "+f"(c[3])
        : "r"(a[0]), "r"(a[1]), "r"(a[2]), "r"(a[3]), "r"(b0), "r"(b1));
}
// fp16-accumulator MMA: D = {d0,d1} packed half2 pairs (row g / row g+8)
__device__ __forceinline__ void mma_f16a(u32& d0, u32& d1, const u32* a, u32 b0, u32 b1) {
    asm volatile("mma.sync.aligned.m16n8k16.row.col.f16.f16.f16.f16 "
        "{%0,%1}, {%2,%3,%4,%5}, {%6,%7}, {%0,%1};"
        : "+r"(d0), "+r"(d1)
        : "r"(a[0]), "r"(a[1]), "r"(a[2]), "r"(a[3]), "r"(b0), "r"(b1));
}
__device__ __forceinline__ void cpa16(u32 s, const void* g) {
    asm volatile("cp.async.cg.shared.global [%0], [%1], 16;" :: "r"(s), "l"(g));
}
#define CP_COMMIT() asm volatile("cp.async.commit_group;" ::: "memory")
#define CP_WAIT1()  asm volatile("cp.async.wait_group 1;" ::: "memory")

__device__ __forceinline__ u32 packh2(float a, float b) {
    __half2 h = __float22half2_rn(make_float2(a, b));
    return *(u32*)&h;
}

// ---------------------------------------------------------------------------
// input conversions: X -> fp16, W(q,k,v) -> fp16, mask -> fp16*log2e
// ---------------------------------------------------------------------------
__global__ __launch_bounds__(256) void convx_kernel(const float* __restrict__ X) {
    size_t i = (size_t)blockIdx.x * 256 + threadIdx.x;
    float4 v = ((const float4*)X)[i];
    uint2 o;
    o.x = packh2(v.x, v.y);
    o.y = packh2(v.z, v.w);
    ((uint2*)g_xf)[i] = o;
}
__global__ __launch_bounds__(256) void convw_kernel(
    const float* __restrict__ qw, const float* __restrict__ kw, const float* __restrict__ vw) {
    const int z = blockIdx.y;
    const float* W = (z == 0) ? qw : (z == 1) ? kw : vw;
    size_t i = (size_t)blockIdx.x * 256 + threadIdx.x;
    float4 v = ((const float4*)W)[i];
    uint2 o;
    o.x = packh2(v.x, v.y);
    o.y = packh2(v.z, v.w);
    ((uint2*)(g_wf + (size_t)z * Dn * Dn))[i] = o;
}
__global__ __launch_bounds__(256) void convm_kernel(const float* __restrict__ mask) {
    int i = blockIdx.x * 256 + threadIdx.x;   // 8192 total
    g_mh[i] = __float2half(mask[i] * LOG2E);
}

// ---------------------------------------------------------------------------
// QKV projection: C = X @ W^T + b, fp16 HMMA (fp32 accum), BK=64.
// 3-stage cp.async, ONE barrier per K-iter: WAIT -> sync -> issue -> compute.
// q rows scaled by 0.125*log2(e) so attention can use exp2.
// ---------------------------------------------------------------------------
#define PBM 128
#define PBN 128
#define PBK 64
#define PST 72
#define XTILE (PBM * PST)
#define PSMEM (3 * 2 * XTILE * 2)     // 110592 B

extern __shared__ char dynsm[];

__global__ __launch_bounds__(256, 2) void qkv_hmma_kernel(
    const float* __restrict__ qb, const float* __restrict__ kb, const float* __restrict__ vb)
{
    const int tid = threadIdx.x, lane = tid & 31, wid = tid >> 5;
    const int z = blockIdx.z;
    const int m0 = blockIdx.y * PBM, n0 = blockIdx.x * PBN;
    const int wm = wid >> 1, wn = wid & 1;
    const int g = lane >> 2, tig = lane & 3;
    const u32 smb = smem_u32(dynsm);

    const __half* Wf = g_wf + (size_t)z * Dn * Dn;
    const float* bias = (z == 0) ? qb : (z == 1) ? kb : vb;
    const float scale = (z == 0) ? 0.125f * LOG2E : 1.0f;
    __half* Of = (z == 0) ? g_qf : (z == 1) ? g_kf : g_vf;

    float C[2][8][4];
#pragma unroll
    for (int mf = 0; mf < 2; mf++)
#pragma unroll
        for (int nt = 0; nt < 8; nt++)
#pragma unroll
            for (int s = 0; s < 4; s++) C[mf][nt][s] = 0.0f;

    auto issue = [&](int ks, int st) {
        const int k0 = ks * PBK;
#pragma unroll
        for (int i = 0; i < 4; i++) {
            int ch = tid + i * 256;
            int row = ch >> 3, c8 = ch & 7;
            u32 so = smb + (u32)(st * 2 * XTILE + row * PST + c8 * 8) * 2;
            cpa16(so, g_xf + (size_t)(m0 + row) * Dn + k0 + c8 * 8);
            cpa16(so + XTILE * 2, Wf + (size_t)(n0 + row) * Dn + k0 + c8 * 8);
        }
        CP_COMMIT();
    };

    issue(0, 0);
    issue(1, 1);

    const int r = lane & 7, sub = lane >> 3;
    const int keyb = ((sub >> 1) & 1) * 8 + r;
    const int dadd = (sub & 1) * 8;

    for (int ks = 0; ks < Dn / PBK; ks++) {
        CP_WAIT1();
        __syncthreads();     // publish stage ks; all reads of stage ks-1 done
        if (ks + 2 < Dn / PBK) issue(ks + 2, (ks + 2) % 3);
        const u32 ab = smb + (u32)((ks % 3) * 2 * XTILE) * 2;
#pragma unroll
        for (int j = 0; j < 4; j++) {
            u32 a[2][4];
#pragma unroll
            for (int mf = 0; mf < 2; mf++) {
                u32 ao = (u32)((wm * 32 + mf * 16 + (lane & 15)) * PST + j * 16 + (lane >> 4) * 8) * 2;
                ldsm_x4(a[mf][0], a[mf][1], a[mf][2], a[mf][3], ab + ao);
            }
            u32 bb[8][2];
#pragma unroll
            for (int p = 0; p < 4; p++) {
                u32 bo = (u32)((wn * 64 + p * 16 + keyb) * PST + j * 16 + dadd) * 2;
                ldsm_x4(bb[2 * p][0], bb[2 * p][1], bb[2 * p + 1][0], bb[2 * p + 1][1],
                        ab + XTILE * 2 + bo);
            }
#pragma unroll
            for (int mf = 0; mf < 2; mf++)
#pragma unroll
                for (int nt = 0; nt < 8; nt++) mma_f16(C[mf][nt], a[mf], bb[nt][0], bb[nt][1]);
        }
    }

    // epilogue: +bias, *scale, fp16, store to [B,H,S,dh]
#pragma unroll
    for (int mf = 0; mf < 2; mf++) {
        const int r0 = m0 + wm * 32 + mf * 16 + g;
#pragma unroll
        for (int nt = 0; nt < 8; nt++) {
            const int c0 = n0 + wn * 64 + nt * 8 + 2 * tig;
            float2 bbv = *(const float2*)(bias + c0);
            const int h = c0 >> 6, dc = c0 & 63;
#pragma unroll
            for (int half = 0; half < 2; half++) {
                const int rr = r0 + half * 8;
                const int b = rr >> 11, s = rr & 2047;
                float x0 = (C[mf][nt][half * 2 + 0] + bbv.x) * scale;
                float x1 = (C[mf][nt][half * 2 + 1] + bbv.y) * scale;
                size_t off = ((size_t)((b * Hn + h) * Sn + s)) * DH + dc;
                *(u32*)(Of + off) = packh2(x0, x1);
            }
        }
    }
}

// ---------------------------------------------------------------------------
// fp16 HMMA flash attention (R14 body). CTA = 128 thr / 4 warps; 32 q rows
// per warp; fp16-accum scores MMA -> in-place softmax (hadd2/h2exp2) -> PV.
// 3-stage cp.async, ONE barrier per KV tile: WAIT -> sync -> issue -> compute.
// ---------------------------------------------------------------------------
#define TKV 64
#define KST 72
#define BUFE (64 * KST)
#define NT (Sn / TKV)
#define AMS_OFF (3 * 2 * BUFE * 2)      // 55296
#define ASMEM (AMS_OFF + 3 * 128)       // + fp16 mask per stage

__global__ __launch_bounds__(128, 3) void attn_hmma_kernel(float* __restrict__ outp)
{
    __half* smbuf = (__half*)dynsm;

    const int tid = threadIdx.x;
    const int lane = tid & 31;
    const int wid = tid >> 5;          // 0..3
    const int bh = blockIdx.y;
    const int b = bh >> 4, h = bh & 15;
    const int q0 = blockIdx.x * 128;
    const int g = lane >> 2;
    const int tig = lane & 3;

    const u32 smb = smem_u32(smbuf);
    const u32 msb = smb + AMS_OFF;
    const __half* mrow = g_mh + (size_t)b * Sn;

    // ---- stage Q (128x64 fp16), ldmatrix into regs ----
#pragma unroll
    for (int i = 0; i < 8; i++) {
        int ch = tid + i * 128;
        int row = ch >> 3, c8 = ch & 7;
        *(uint4*)(smbuf + row * KST + c8 * 8) =
            *(const uint4*)(g_qf + ((size_t)bh * Sn + q0 + row) * DH + c8 * 8);
    }
    __syncthreads();

    u32 qf[2][4][4];
#pragma unroll
    for (int mf = 0; mf < 2; mf++) {
        int row = wid * 32 + mf * 16 + (lane & 15);
        int cb = (lane >> 4) * 8;
#pragma unroll
        for (int j = 0; j < 4; j++) {
            u32 ao = (u32)(row * KST + j * 16 + cb) * 2;
            ldsm_x4(qf[mf][j][0], qf[mf][j][1], qf[mf][j][2], qf[mf][j][3], smb + ao);
        }
    }
    __syncthreads();

    auto issue = [&](int t, int st) {
        const int t0 = t * TKV;
        const u32 sb = smb + (u32)(st * 2 * BUFE) * 2;
#pragma unroll
        for (int i = 0; i < 4; i++) {
            int ch = tid + i * 128;
            int row = ch >> 3, c8 = ch & 7;
            size_t gix = ((size_t)bh * Sn + t0 + row) * DH + c8 * 8;
            u32 so = sb + (u32)(row * KST + c8 * 8) * 2;
            cpa16(so, g_kf + gix);
            cpa16(so + BUFE * 2, g_vf + gix);
        }
        if (tid < 8) cpa16(msb + st * 128 + tid * 16, mrow + t0 + tid * 8);
        CP_COMMIT();
    };

    issue(0, 0);
    issue(1, 1);

    float ctx[2][8][4];
#pragma unroll
    for (int mf = 0; mf < 2; mf++)
#pragma unroll
        for (int m = 0; m < 8; m++)
#pragma unroll
            for (int s = 0; s < 4; s++) ctx[mf][m][s] = 0.0f;
    float ls[2][2] = {{0.0f, 0.0f}, {0.0f, 0.0f}};

    const int r = lane & 7, sub = lane >> 3;
    const int keyb = ((sub >> 1) & 1) * 8 + r;       // scores B mapping
    const int dadds = (sub & 1) * 8;
    const int keyadd = (sub & 1) * 8 + r;            // PV B mapping
    const int daddv = ((sub >> 1) & 1) * 8;

#pragma unroll 1
    for (int t = 0; t < NT; t++) {
        CP_WAIT1();
        __syncthreads();     // publish stage t; all reads of stage t-1 done
        if (t + 2 < NT) issue(t + 2, (t + 2) % 3);
        const int st = t % 3;
        const u32 kf_b = smb + (u32)(st * 2 * BUFE) * 2;
        const u32 vf_b = kf_b + BUFE * 2;

        // ---- scores S = Q*K^T, fp16 accum (2 m-frags x 8 n-tiles) ----
        u32 Cp[2][8][2];
#pragma unroll
        for (int mf = 0; mf < 2; mf++)
#pragma unroll
            for (int nt = 0; nt < 8; nt++) { Cp[mf][nt][0] = 0u; Cp[mf][nt][1] = 0u; }
#pragma unroll
        for (int j = 0; j < 4; j++) {
            u32 bk[8][2];
#pragma unroll
            for (int p = 0; p < 4; p++) {
                u32 ao = (u32)((p * 16 + keyb) * KST + j * 16 + dadds) * 2;
                ldsm_x4(bk[2 * p][0], bk[2 * p][1], bk[2 * p + 1][0], bk[2 * p + 1][1], kf_b + ao);
            }
#pragma unroll
            for (int mf = 0; mf < 2; mf++)
#pragma unroll
                for (int nt = 0; nt < 8; nt++)
                    mma_f16a(Cp[mf][nt][0], Cp[mf][nt][1], qf[mf][j], bk[nt][0], bk[nt][1]);
        }

        // ---- softmax in place: +mask(log2e, fp16), h2exp2, hadd2 lsum ----
        {
            const __half2* mp = (const __half2*)(dynsm + AMS_OFF + st * 128);
            __half2 lt[2][2];
            lt[0][0] = __float2half2_rn(0.0f); lt[0][1] = lt[0][0];
            lt[1][0] = lt[0][0];               lt[1][1] = lt[0][0];
#pragma unroll
            for (int nt = 0; nt < 8; nt++) {
                __half2 mh = mp[nt * 4 + tig];
#pragma unroll
                for (int mf = 0; mf < 2; mf++) {
                    __half2 p0 = h2exp2(__hadd2(*(__half2*)&Cp[mf][nt][0], mh));
                    __half2 p1 = h2exp2(__hadd2(*(__half2*)&Cp[mf][nt][1], mh));
                    lt[mf][0] = __hadd2(lt[mf][0], p0);
                    lt[mf][1] = __hadd2(lt[mf][1], p1);
                    Cp[mf][nt][0] = *(u32*)&p0;
                    Cp[mf][nt][1] = *(u32*)&p1;
                }
            }
#pragma unroll
            for (int mf = 0; mf < 2; mf++) {
                float2 f01 = __half22float2(lt[mf][0]);
                float2 f23 = __half22float2(lt[mf][1]);
                ls[mf][0] += f01.x + f01.y;
                ls[mf][1] += f23.x + f23.y;
            }
        }

        // ---- ctx += P*V (A frags = Cp[mf][2j..2j+1], contiguous) ----
#pragma unroll
        for (int j = 0; j < 4; j++) {
            u32 vv[8][2];
#pragma unroll
            for (int p = 0; p < 4; p++) {
                u32 ao = (u32)((j * 16 + keyadd) * KST + p * 16 + daddv) * 2;
                ldsm_x4_t(vv[2 * p][0], vv[2 * p][1], vv[2 * p + 1][0], vv[2 * p + 1][1], vf_b + ao);
            }
#pragma unroll
            for (int mf = 0; mf < 2; mf++)
#pragma unroll
                for (int m = 0; m < 8; m++)
                    mma_f16(ctx[mf][m], &Cp[mf][2 * j][0], vv[m][0], vv[m][1]);
        }
    }

    // ---- finalize: quad-reduce row sums, normalize, store ----
#pragma unroll
    for (int mf = 0; mf < 2; mf++) {
        float l0 = ls[mf][0], l1 = ls[mf][1];
        l0 += __shfl_xor_sync(0xffffffff, l0, 1);
        l0 += __shfl_xor_sync(0xffffffff, l0, 2);
        l1 += __shfl_xor_sync(0xffffffff, l1, 1);
        l1 += __shfl_xor_sync(0xffffffff, l1, 2);
        const float inv0 = 1.0f / l0, inv1 = 1.0f / l1;

        const int row0 = q0 + wid * 32 + mf * 16 + g;
        const int row1 = row0 + 8;
        float* d0 = outp + (size_t)(b * Sn + row0) * Dn + h * DH + 2 * tig;
        float* d1 = outp + (size_t)(b * Sn + row1) * Dn + h * DH + 2 * tig;
#pragma unroll
        for (int m = 0; m < 8; m++) {
            *(float2*)(d0 + m * 8) = make_float2(ctx[mf][m][0] * inv0, ctx[mf][m][1] * inv0);
            *(float2*)(d1 + m * 8) = make_float2(ctx[mf][m][2] * inv1, ctx[mf][m][3] * inv1);
        }
    }
}

// ---------------------------------------------------------------------------
extern "C" void kernel_launch(void* const* d_in, const int* in_sizes, int n_in,
                              void* d_out, int out_size)
{
    (void)in_sizes; (void)n_in; (void)out_size;
    const float* X    = (const float*)d_in[0];
    const float* mask = (const float*)d_in[1];
    const float* qw   = (const float*)d_in[2];
    const float* qb   = (const float*)d_in[3];
    const float* kw   = (const float*)d_in[4];
    const float* kb   = (const float*)d_in[5];
    const float* vw   = (const float*)d_in[6];
    const float* vb   = (const float*)d_in[7];
    float* out = (float*)d_out;

    static int attr_done = 0;
    if (!attr_done) {
        cudaFuncSetAttribute(qkv_hmma_kernel,
                             cudaFuncAttributeMaxDynamicSharedMemorySize, PSMEM);
        cudaFuncSetAttribute(attn_hmma_kernel,
                             cudaFuncAttributeMaxDynamicSharedMemorySize, ASMEM);
        attr_done = 1;
    }

    convx_kernel<<<(Bn * Sn * Dn) / 4 / 256, 256>>>(X);
    convw_kernel<<<dim3((Dn * Dn) / 4 / 256, 3), 256>>>(qw, kw, vw);
    convm_kernel<<<(Bn * Sn) / 256, 256>>>(mask);

    qkv_hmma_kernel<<<dim3(Dn / PBN, (Bn * Sn) / PBM, 3), 256, PSMEM>>>(qb, kb, vb);

    attn_hmma_kernel<<<dim3(Sn / 128, Bn * Hn), 128, ASMEM>>>(out);
}